// round 14
// baseline (speedup 1.0000x reference)
#include <cuda_runtime.h>
#include <math.h>

#define MAX_IN 64
#define D_MODEL 64
#define THREADS 256
#define NBLOCKS (148 * 6)
#define GPB (THREADS / 16)              // 16 groups per block
#define TOTAL_GROUPS (NBLOCKS * GPB)    // 14208

__device__ int g_ctr;

__device__ __forceinline__ float fast_tanh(float x) {
    float y;
    asm("tanh.approx.f32 %0, %1;" : "=f"(y) : "f"(x));
    return y;
}

__device__ __forceinline__ float gelu_tanh(float v) {
    const float c = 0.7978845608028654f;
    float u = c * (v + 0.044715f * v * v * v);
    return 0.5f * v * (1.0f + fast_tanh(u));
}

__global__ __launch_bounds__(THREADS, 6)
void fe_kernel(const float* __restrict__ seg,
               const float* __restrict__ W,
               const float* __restrict__ b,
               const int*   __restrict__ lengths,
               float* __restrict__ out,
               int n)
{
    const int tid    = threadIdx.x;
    const int t      = tid & 15;                 // d-chunk (float4 over D_MODEL)
    const int lane   = tid & 31;
    const unsigned m16 = (lane < 16) ? 0x0000FFFFu : 0xFFFF0000u;
    const int leader = lane & 16;                // leader lane id within warp

    // static first row per group, then steal
    int row = blockIdx.x * GPB + (tid >> 4);

    while (row < n) {
        // issue the steal for the NEXT row now; latency hides under this row
        int nxt = 0;
        if ((lane & 15) == 0) nxt = TOTAL_GROUPS + atomicAdd(&g_ctr, 1);

        const int len = __ldg(lengths + row);    // broadcast across group
        const float4* Wr = reinterpret_cast<const float4*>(W) + (size_t)row * 1024 + t;
        const float4* xq = reinterpret_cast<const float4*>(seg) + (size_t)row * 16;

        float4 acc = make_float4(0.f, 0.f, 0.f, 0.f);
        const int full = len >> 2;
        const int rem  = len & 3;

        // full 4-wide batches: 4 independent LDG.128 in flight
        #pragma unroll 1
        for (int j = 0; j < full; ++j) {
            const float4* wp = Wr + j * 64;
            float4 w0 = wp[0];
            float4 w1 = wp[16];
            float4 w2 = wp[32];
            float4 w3 = wp[48];
            float4 xv = __ldg(xq + j);           // 16B broadcast
            acc.x += xv.x * w0.x + xv.y * w1.x + xv.z * w2.x + xv.w * w3.x;
            acc.y += xv.x * w0.y + xv.y * w1.y + xv.z * w2.y + xv.w * w3.y;
            acc.z += xv.x * w0.z + xv.y * w1.z + xv.z * w2.z + xv.w * w3.z;
            acc.w += xv.x * w0.w + xv.y * w1.w + xv.z * w2.w + xv.w * w3.w;
        }
        // remainder as ONE more full-width batch with x masked in registers
        if (rem) {
            const float4* wp = Wr + full * 64;
            float4 w0 = wp[0];
            float4 w1 = wp[16];
            float4 w2 = wp[32];
            float4 w3 = wp[48];
            float4 xv = __ldg(xq + full);
            if (rem < 2) xv.y = 0.f;
            if (rem < 3) xv.z = 0.f;
            xv.w = 0.f;                           // rem <= 3 always here
            acc.x += xv.x * w0.x + xv.y * w1.x + xv.z * w2.x + xv.w * w3.x;
            acc.y += xv.x * w0.y + xv.y * w1.y + xv.z * w2.y + xv.w * w3.y;
            acc.z += xv.x * w0.z + xv.y * w1.z + xv.z * w2.z + xv.w * w3.z;
            acc.w += xv.x * w0.w + xv.y * w1.w + xv.z * w2.w + xv.w * w3.w;
        }

        float4 bb = __ldg(reinterpret_cast<const float4*>(b) + (size_t)row * 16 + t);
        float4 r4;
        r4.x = gelu_tanh(acc.x + bb.x);
        r4.y = gelu_tanh(acc.y + bb.y);
        r4.z = gelu_tanh(acc.z + bb.z);
        r4.w = gelu_tanh(acc.w + bb.w);
        reinterpret_cast<float4*>(out)[(size_t)row * 16 + t] = r4;

        // advance to stolen row
        nxt = __shfl_sync(m16, nxt, leader);
        row = nxt;
    }
}

extern "C" void kernel_launch(void* const* d_in, const int* in_sizes, int n_in,
                              void* d_out, int out_size) {
    const float* seg     = (const float*)d_in[0];
    const float* W       = (const float*)d_in[1];
    const float* b       = (const float*)d_in[2];
    const int*   lengths = (const int*)d_in[3];
    float* out = (float*)d_out;

    int n = in_sizes[3];

    void* ctr_ptr = nullptr;
    cudaGetSymbolAddress(&ctr_ptr, g_ctr);
    cudaMemsetAsync(ctr_ptr, 0, sizeof(int));   // graph-capturable memset node

    fe_kernel<<<NBLOCKS, THREADS>>>(seg, W, b, lengths, out, n);
}